// round 4
// baseline (speedup 1.0000x reference)
#include <cuda_runtime.h>
#include <math.h>

// LIF_R step, N=8192. Dominant cost: w @ g (256 MB fp32, streamed once).
// R4: one CTA per row, static round-robin over 912 persistent CTAs
// (6/SM * 152 SMs) -> near-perfect load balance (8.98 rows/CTA), no tail.
// g staged in smem; single __syncthreads per row via parity-double-buffered
// warp-partial array.

#define N_NEURONS 8192
#define NF4 (N_NEURONS / 4)              // 2048 float4 per row
#define THREADS 256
#define WARPS (THREADS / 32)
#define GRID 912                          // 6 CTAs/SM * 152 SMs

#define C_M_INV 20.0f
#define F_V 0.15f
#define DELTA_V 12.0f

__global__ __launch_bounds__(THREADS, 6)
void lif_r_kernel(const float* __restrict__ x_in,
                  const float* __restrict__ v,
                  const float* __restrict__ g,
                  const float* __restrict__ theta_s,
                  const float* __restrict__ w,
                  const float* __restrict__ v_rest,
                  float* __restrict__ out)
{
    __shared__ float sg[N_NEURONS];       // 32 KB
    __shared__ float sred[2][WARPS];      // parity double-buffered partials

    // Stage g into shared once
    {
        const float4* g4 = reinterpret_cast<const float4*>(g);
        float4* s4 = reinterpret_cast<float4*>(sg);
        for (int i = threadIdx.x; i < NF4; i += THREADS)
            s4[i] = g4[i];
    }
    __syncthreads();

    const int tid  = threadIdx.x;
    const int lane = tid & 31;
    const int wid  = tid >> 5;
    const float4* __restrict__ sg4 = reinterpret_cast<const float4*>(sg);

    for (int row = blockIdx.x; row < N_NEURONS; row += GRID) {
        const float4* __restrict__ wrow =
            reinterpret_cast<const float4*>(w + (size_t)row * N_NEURONS);

        // 2048 float4 / 256 threads = 8 per thread; two 4-deep batches.
        float a0 = 0.0f, a1 = 0.0f;
        #pragma unroll
        for (int k = 0; k < 8; k += 4) {
            const int b = tid + k * THREADS;
            float4 w0 = __ldcs(&wrow[b]);
            float4 w1 = __ldcs(&wrow[b + THREADS]);
            float4 w2 = __ldcs(&wrow[b + 2 * THREADS]);
            float4 w3 = __ldcs(&wrow[b + 3 * THREADS]);
            float4 g0 = sg4[b];
            float4 g1 = sg4[b + THREADS];
            float4 g2 = sg4[b + 2 * THREADS];
            float4 g3 = sg4[b + 3 * THREADS];
            a0 = fmaf(w0.x, g0.x, a0); a0 = fmaf(w0.y, g0.y, a0);
            a0 = fmaf(w0.z, g0.z, a0); a0 = fmaf(w0.w, g0.w, a0);
            a1 = fmaf(w1.x, g1.x, a1); a1 = fmaf(w1.y, g1.y, a1);
            a1 = fmaf(w1.z, g1.z, a1); a1 = fmaf(w1.w, g1.w, a1);
            a0 = fmaf(w2.x, g2.x, a0); a0 = fmaf(w2.y, g2.y, a0);
            a0 = fmaf(w2.z, g2.z, a0); a0 = fmaf(w2.w, g2.w, a0);
            a1 = fmaf(w3.x, g3.x, a1); a1 = fmaf(w3.y, g3.y, a1);
            a1 = fmaf(w3.z, g3.z, a1); a1 = fmaf(w3.w, g3.w, a1);
        }
        float acc = a0 + a1;

        #pragma unroll
        for (int off = 16; off > 0; off >>= 1)
            acc += __shfl_xor_sync(0xFFFFFFFFu, acc, off);

        const int par = row & 1;
        if (lane == 0) sred[par][wid] = acc;
        __syncthreads();

        if (tid == 0) {
            float s = sred[par][0];
            #pragma unroll
            for (int i = 1; i < WARPS; i++) s += sred[par][i];

            const float I  = s + x_in[row];
            const float vv = v[row];
            const float vr = v_rest[row];
            const float th = theta_s[row];

            const float v_next = vv + (vr - vv + I * C_M_INV);
            const float soft = 1.0f / (1.0f + expf(-(v_next - th)));
            const bool spiked = (v_next >= th);
            const float v_reset = vr + F_V * (vv - vr) - DELTA_V;
            const float v_new = spiked ? v_reset : v_next;

            out[row] = v_new;
            out[N_NEURONS + row] = soft;
        }
        // No second sync: next row writes the other parity buffer, and the
        // sync at the next iteration orders the read above vs. the write
        // two rows ahead.
    }
}

extern "C" void kernel_launch(void* const* d_in, const int* in_sizes, int n_in,
                              void* d_out, int out_size)
{
    // metadata order: x_in, v, g, theta_s, w, v_rest, tau_g
    const float* x_in    = (const float*)d_in[0];
    const float* v       = (const float*)d_in[1];
    const float* g       = (const float*)d_in[2];
    const float* theta_s = (const float*)d_in[3];
    const float* w       = (const float*)d_in[4];
    const float* v_rest  = (const float*)d_in[5];
    float* out = (float*)d_out;

    lif_r_kernel<<<GRID, THREADS>>>(x_in, v, g, theta_s, w, v_rest, out);
}

// round 5
// speedup vs baseline: 1.2062x; 1.2062x over previous
#include <cuda_runtime.h>
#include <math.h>

// LIF_R step, N=8192. w @ g dominates: 256 MB fp32 streamed once from HBM.
// R5: warp-per-row, barrier-free (like R3), but exact balance: 4096 warps,
// each fusing rows r and r+4096 in one loop (shared g reads, 2 acc chains,
// 2x MLP). Single wave: 512 CTAs <= 4/SM * 152 SMs.

#define N_NEURONS 8192
#define NF4 (N_NEURONS / 4)          // 2048 float4 per row
#define THREADS 256
#define WARPS_PER_CTA 8
#define GRID 512                      // 4096 warps -> exactly 2 rows/warp
#define HALF 4096                     // row stride between a warp's two rows

#define C_M_INV 20.0f
#define F_V 0.15f
#define DELTA_V 12.0f

__global__ __launch_bounds__(THREADS, 4)
void lif_r_kernel(const float* __restrict__ x_in,
                  const float* __restrict__ v,
                  const float* __restrict__ g,
                  const float* __restrict__ theta_s,
                  const float* __restrict__ w,
                  const float* __restrict__ v_rest,
                  float* __restrict__ out)
{
    __shared__ float sg[N_NEURONS];   // 32 KB

    // Stage g into shared once per CTA
    {
        const float4* g4 = reinterpret_cast<const float4*>(g);
        float4* s4 = reinterpret_cast<float4*>(sg);
        for (int i = threadIdx.x; i < NF4; i += THREADS)
            s4[i] = g4[i];
    }
    __syncthreads();

    const int lane = threadIdx.x & 31;
    const int wid  = threadIdx.x >> 5;
    const int row0 = blockIdx.x * WARPS_PER_CTA + wid;   // 0..4095
    const int row1 = row0 + HALF;                        // 4096..8191

    const float4* __restrict__ sg4 = reinterpret_cast<const float4*>(sg);
    const float4* __restrict__ wr0 =
        reinterpret_cast<const float4*>(w + (size_t)row0 * N_NEURONS);
    const float4* __restrict__ wr1 =
        reinterpret_cast<const float4*>(w + (size_t)row1 * N_NEURONS);

    // 2048 float4 / 32 lanes = 64 iters/lane; 2 rows fused; unroll 2
    // -> 4 LDG.128 front-batched per step, 2 independent FMA chains/row.
    float a0 = 0.0f, a1 = 0.0f, b0 = 0.0f, b1 = 0.0f;
    #pragma unroll 2
    for (int i = lane; i < NF4; i += 64) {
        float4 wa0 = __ldcs(&wr0[i]);
        float4 wb0 = __ldcs(&wr1[i]);
        float4 wa1 = __ldcs(&wr0[i + 32]);
        float4 wb1 = __ldcs(&wr1[i + 32]);
        float4 g0 = sg4[i];
        float4 g1 = sg4[i + 32];
        a0 = fmaf(wa0.x, g0.x, a0); a0 = fmaf(wa0.y, g0.y, a0);
        a0 = fmaf(wa0.z, g0.z, a0); a0 = fmaf(wa0.w, g0.w, a0);
        b0 = fmaf(wb0.x, g0.x, b0); b0 = fmaf(wb0.y, g0.y, b0);
        b0 = fmaf(wb0.z, g0.z, b0); b0 = fmaf(wb0.w, g0.w, b0);
        a1 = fmaf(wa1.x, g1.x, a1); a1 = fmaf(wa1.y, g1.y, a1);
        a1 = fmaf(wa1.z, g1.z, a1); a1 = fmaf(wa1.w, g1.w, a1);
        b1 = fmaf(wb1.x, g1.x, b1); b1 = fmaf(wb1.y, g1.y, b1);
        b1 = fmaf(wb1.z, g1.z, b1); b1 = fmaf(wb1.w, g1.w, b1);
    }
    float accA = a0 + a1;
    float accB = b0 + b1;

    #pragma unroll
    for (int off = 16; off > 0; off >>= 1) {
        accA += __shfl_xor_sync(0xFFFFFFFFu, accA, off);
        accB += __shfl_xor_sync(0xFFFFFFFFu, accB, off);
    }

    if (lane == 0) {
        // row0
        {
            const float I  = accA + x_in[row0];
            const float vv = v[row0];
            const float vr = v_rest[row0];
            const float th = theta_s[row0];
            const float v_next = vv + (vr - vv + I * C_M_INV);
            const float soft = 1.0f / (1.0f + expf(-(v_next - th)));
            const bool spiked = (v_next >= th);
            const float v_reset = vr + F_V * (vv - vr) - DELTA_V;
            out[row0] = spiked ? v_reset : v_next;
            out[N_NEURONS + row0] = soft;
        }
        // row1
        {
            const float I  = accB + x_in[row1];
            const float vv = v[row1];
            const float vr = v_rest[row1];
            const float th = theta_s[row1];
            const float v_next = vv + (vr - vv + I * C_M_INV);
            const float soft = 1.0f / (1.0f + expf(-(v_next - th)));
            const bool spiked = (v_next >= th);
            const float v_reset = vr + F_V * (vv - vr) - DELTA_V;
            out[row1] = spiked ? v_reset : v_next;
            out[N_NEURONS + row1] = soft;
        }
    }
}

extern "C" void kernel_launch(void* const* d_in, const int* in_sizes, int n_in,
                              void* d_out, int out_size)
{
    // metadata order: x_in, v, g, theta_s, w, v_rest, tau_g
    const float* x_in    = (const float*)d_in[0];
    const float* v       = (const float*)d_in[1];
    const float* g       = (const float*)d_in[2];
    const float* theta_s = (const float*)d_in[3];
    const float* w       = (const float*)d_in[4];
    const float* v_rest  = (const float*)d_in[5];
    float* out = (float*)d_out;

    lif_r_kernel<<<GRID, THREADS>>>(x_in, v, g, theta_s, w, v_rest, out);
}